// round 13
// baseline (speedup 1.0000x reference)
#include <cuda_runtime.h>
#include <cstddef>
#include <cstdint>

// Problem constants
#define BB    128
#define DD    128
#define OUTSZ 100000
#define KP1   4097
#define NP    (BB * KP1)          // 524416 score elements per memory
#define INV_T (1.0f / 0.07f)
#define MEMN  ((size_t)OUTSZ * DD)
#define NHITS (BB * KP1)

// Inverted-index bucket capacity per row. Hits/row ~ Poisson(5.25);
// P(>64) ~ 1e-40 over the fixed dataset -> effectively impossible.
#define CAP   64

// Main kernel geometry: 3 blocks/SM x 148 SMs
#define NBLK    444
#define ROWS_PB 226   // ceil(100000/444)

// Output layout (float32):
#define OFF_I2   ((size_t)0)
#define OFF_I3   ((size_t)NP)
#define OFF_M2   ((size_t)2 * NP)
#define OFF_M3   ((size_t)2 * NP + MEMN)

// Scratch (all fully rewritten or re-zeroed every launch -> graph-safe)
__device__ int      g_count[OUTSZ];
__device__ unsigned g_list[(size_t)OUTSZ * CAP];   // packed (k<<7)|b
__device__ float    g_part[2 * NBLK];

// ---------------------------------------------------------------------------
// Zero the per-row hit counters.
// ---------------------------------------------------------------------------
__global__ void zero_kernel()
{
    const int i = blockIdx.x * blockDim.x + threadIdx.x;
    if (i < OUTSZ) g_count[i] = 0;
}

// ---------------------------------------------------------------------------
// Build the inverted index: for every (b,k) pair, append (k<<7)|b to the
// bucket of its row. k==0 uses y[b] (idx[:,0] is replaced by y).
// ---------------------------------------------------------------------------
__global__ void build_kernel(const int* __restrict__ y,
                             const int* __restrict__ idx)
{
    const int i = blockIdx.x * blockDim.x + threadIdx.x;
    if (i >= NHITS) return;
    const int b = i / KP1;
    const int k = i - b * KP1;
    int row = (k == 0) ? y[b] : idx[i];
    row = row < 0 ? 0 : (row >= OUTSZ ? OUTSZ - 1 : row);
    const int c = atomicAdd(&g_count[row], 1);
    if (c < CAP)
        g_list[(size_t)row * CAP + c] = ((unsigned)k << 7) | (unsigned)b;
}

// ---------------------------------------------------------------------------
// Main kernel: ONE streaming pass over both banks. Each warp takes rows
// (stride 8 within its block's range). Per row: load the 512B row of each
// bank (1 float4/lane), write the copy, then for each hit compute BOTH
// dots against z1[b] (z1 resident in 64KB dynamic smem), exp, scatter.
// ---------------------------------------------------------------------------
template <bool VEC>
__global__ void __launch_bounds__(256, 3) main_kernel(
    const float* __restrict__ z1,
    const float* __restrict__ mem2,
    const float* __restrict__ mem3,
    float*       __restrict__ out)
{
    extern __shared__ float4 z1s[];     // [DD*32] = 64KB: z1[b] row = z1s[b*32 + lane]
    __shared__ float red2[256], red3[256];

    const int tid = threadIdx.x;

    // Cooperative z1 load into smem
    if (VEC) {
        const float4* __restrict__ z4 = (const float4*)z1;
        for (int i = tid; i < DD * 32; i += 256) z1s[i] = z4[i];
    } else {
        for (int i = tid; i < DD * 32; i += 256) {
            const float* p = z1 + i * 4;
            float4 v; v.x = p[0]; v.y = p[1]; v.z = p[2]; v.w = p[3];
            z1s[i] = v;
        }
    }
    __syncthreads();

    const int warp = tid >> 5;
    const int l    = tid & 31;

    const int rb = blockIdx.x * ROWS_PB;
    int re = rb + ROWS_PB;
    if (re > OUTSZ) re = OUTSZ;

    float* __restrict__ om2 = out + OFF_M2;
    float* __restrict__ om3 = out + OFF_M3;

    float acc2 = 0.0f, acc3 = 0.0f;

    for (int r = rb + warp; r < re; r += 8) {
        // load bank rows (512B each, 1 float4 per lane)
        float4 a, c;
        if (VEC) {
            a = ((const float4*)(mem2 + (size_t)r * DD))[l];
            c = ((const float4*)(mem3 + (size_t)r * DD))[l];
        } else {
            const float* p2 = mem2 + (size_t)r * DD + l * 4;
            a.x = p2[0]; a.y = p2[1]; a.z = p2[2]; a.w = p2[3];
            const float* p3 = mem3 + (size_t)r * DD + l * 4;
            c.x = p3[0]; c.y = p3[1]; c.z = p3[2]; c.w = p3[3];
        }

        // copy-out (streaming stores)
        if (VEC) {
            __stcs(&((float4*)(om2 + (size_t)r * DD))[l], a);
            __stcs(&((float4*)(om3 + (size_t)r * DD))[l], c);
        } else {
            float* q2 = om2 + (size_t)r * DD + l * 4;
            q2[0] = a.x; q2[1] = a.y; q2[2] = a.z; q2[3] = a.w;
            float* q3 = om3 + (size_t)r * DD + l * 4;
            q3[0] = c.x; q3[1] = c.y; q3[2] = c.z; q3[3] = c.w;
        }

        // hits for this row
        int cnt = g_count[r];
        if (cnt > CAP) cnt = CAP;
        const unsigned* __restrict__ lst = g_list + (size_t)r * CAP;

        for (int j = 0; j < cnt; ++j) {
            const unsigned u = lst[j];          // uniform broadcast load
            const int b = (int)(u & 127u);
            const int k = (int)(u >> 7);

            const float4 zv = z1s[b * 32 + l];
            float d2 = a.x * zv.x;
            d2 = fmaf(a.y, zv.y, d2);
            d2 = fmaf(a.z, zv.z, d2);
            d2 = fmaf(a.w, zv.w, d2);
            float d3 = c.x * zv.x;
            d3 = fmaf(c.y, zv.y, d3);
            d3 = fmaf(c.z, zv.z, d3);
            d3 = fmaf(c.w, zv.w, d3);

            // interleaved full-warp reductions (converged)
            #pragma unroll
            for (int off = 16; off > 0; off >>= 1) {
                d2 += __shfl_xor_sync(0xffffffffu, d2, off);
                d3 += __shfl_xor_sync(0xffffffffu, d3, off);
            }

            if (l == 0) {
                const float s2 = __expf(d2 * INV_T);
                const float s3 = __expf(d3 * INV_T);
                __stcs(&out[OFF_I2 + (size_t)b * KP1 + k], s2);
                __stcs(&out[OFF_I3 + (size_t)b * KP1 + k], s3);
                acc2 += s2;
                acc3 += s3;
            }
        }
    }

    // block reduction of Z partials
    red2[tid] = acc2;
    red3[tid] = acc3;
    __syncthreads();
    for (int off = 128; off > 0; off >>= 1) {
        if (tid < off) {
            red2[tid] += red2[tid + off];
            red3[tid] += red3[tid + off];
        }
        __syncthreads();
    }
    if (tid == 0) {
        g_part[blockIdx.x]        = red2[0];
        g_part[NBLK + blockIdx.x] = red3[0];
    }
}

// ---------------------------------------------------------------------------
// Normalize: each block redundantly reduces the per-block partials, then
// scales its grid-stride slice of the scores.
// ---------------------------------------------------------------------------
#define NORM_BLOCKS 1024
__global__ void __launch_bounds__(256) norm_kernel(float* __restrict__ out)
{
    const int tid = threadIdx.x;
    float s0 = 0.0f, s1 = 0.0f;
    for (int i = tid; i < NBLK; i += 256) {
        s0 += g_part[i];
        s1 += g_part[NBLK + i];
    }
    __shared__ float r0[256], r1[256];
    r0[tid] = s0; r1[tid] = s1;
    __syncthreads();
    for (int off = 128; off > 0; off >>= 1) {
        if (tid < off) { r0[tid] += r0[tid + off]; r1[tid] += r1[tid + off]; }
        __syncthreads();
    }
    const float inv0 = 1.0f / (r0[0] / (float)NP * (float)OUTSZ);
    const float inv1 = 1.0f / (r1[0] / (float)NP * (float)OUTSZ);

    const int stride = NORM_BLOCKS * 256;
    for (int i = blockIdx.x * 256 + tid; i < 2 * NP; i += stride)
        __stcs(&out[i], out[i] * ((i < NP) ? inv0 : inv1));
}

// ---------------------------------------------------------------------------
// Memory-row update: pos = 2*z - mem[y]; L2-normalize; scatter (last
// duplicate wins via predicated store). Runs after main (copies done).
// ---------------------------------------------------------------------------
__global__ void update_kernel(
    const float* __restrict__ z2,
    const float* __restrict__ z3,
    const float* __restrict__ mem2,
    const float* __restrict__ mem3,
    const int*   __restrict__ y,
    float*       __restrict__ out)
{
    const int i = blockIdx.x;   // batch row 0..127
    const int m = blockIdx.y;   // memory select
    const int d = threadIdx.x;  // 128 threads = D

    int yi = y[i];
    yi = yi < 0 ? 0 : (yi >= OUTSZ ? OUTSZ - 1 : yi);
    bool dead = false;
    for (int j = i + 1; j < BB; ++j)
        dead = dead || (y[j] == yi);

    const float* __restrict__ mem = m ? mem3 : mem2;
    const float* __restrict__ z   = m ? z3   : z2;

    const float v = 2.0f * z[i * DD + d] - mem[(size_t)yi * DD + d];

    __shared__ float ss[DD];
    ss[d] = v * v;
    __syncthreads();
    for (int off = 64; off > 0; off >>= 1) {
        if (d < off) ss[d] += ss[d + off];
        __syncthreads();
    }
    const float inv = 1.0f / sqrtf(ss[0]);

    if (!dead) {
        float* __restrict__ om = out + (m ? OFF_M3 : OFF_M2);
        om[(size_t)yi * DD + d] = v * inv;
    }
}

extern "C" void kernel_launch(void* const* d_in, const int* in_sizes, int n_in,
                              void* d_out, int out_size)
{
    // Identify inputs BY ELEMENT COUNT (order-robust):
    const float* zv[3]   = {0, 0, 0};
    const float* memv[2] = {0, 0};
    const int*   y   = 0;
    const int*   idx = 0;
    int nz = 0, nm = 0;
    for (int i = 0; i < n_in; ++i) {
        const int sz = in_sizes[i];
        if (sz == BB * DD) {
            if (nz < 3) zv[nz++] = (const float*)d_in[i];
        } else if (sz == (int)MEMN) {
            if (nm < 2) memv[nm++] = (const float*)d_in[i];
        } else if (sz == BB) {
            y = (const int*)d_in[i];
        } else if (sz == BB * KP1) {
            idx = (const int*)d_in[i];
        }
    }
    const float* z1   = zv[0];
    const float* z2   = zv[1];
    const float* z3   = zv[2];
    const float* mem2 = memv[0];
    const float* mem3 = memv[1];
    float* out = (float*)d_out;

    const bool vec = ((((uintptr_t)mem2) | ((uintptr_t)mem3)
                     | ((uintptr_t)z1) | ((uintptr_t)out)) & 0xF) == 0;

    // One-time setup: side stream, events, smem opt-in for the 64KB z1 tile.
    static cudaStream_t sB = 0;
    static cudaEvent_t evFork = 0, evJoin = 0;
    if (sB == 0) {
        cudaStreamCreateWithFlags(&sB, cudaStreamNonBlocking);
        cudaEventCreateWithFlags(&evFork, cudaEventDisableTiming);
        cudaEventCreateWithFlags(&evJoin, cudaEventDisableTiming);
        cudaFuncSetAttribute((const void*)main_kernel<true>,
                             cudaFuncAttributeMaxDynamicSharedMemorySize, 65536);
        cudaFuncSetAttribute((const void*)main_kernel<false>,
                             cudaFuncAttributeMaxDynamicSharedMemorySize, 65536);
    }

    // 1) reset per-row counters
    zero_kernel<<<(OUTSZ + 255) / 256, 256>>>();

    // 2) build inverted index (row -> list of (b,k))
    build_kernel<<<(NHITS + 255) / 256, 256>>>(y, idx);

    // 3) single streaming pass: copy banks + all dots/exp/scatter
    if (vec)
        main_kernel<true ><<<NBLK, 256, 65536>>>(z1, mem2, mem3, out);
    else
        main_kernel<false><<<NBLK, 256, 65536>>>(z1, mem2, mem3, out);

    // Fork: update (needs copies) on side stream, norm (needs scores) on main.
    cudaEventRecord(evFork, 0);
    cudaStreamWaitEvent(sB, evFork, 0);

    dim3 ugrid(BB, 2);
    update_kernel<<<ugrid, DD, 0, sB>>>(z2, z3, mem2, mem3, y, out);
    cudaEventRecord(evJoin, sB);

    norm_kernel<<<NORM_BLOCKS, 256>>>(out);

    cudaStreamWaitEvent(0, evJoin, 0);
}

// round 14
// speedup vs baseline: 1.4971x; 1.4971x over previous
#include <cuda_runtime.h>
#include <cstddef>
#include <cstdint>

// Problem constants
#define BB    128
#define DD    128
#define OUTSZ 100000
#define KP1   4097
#define NP    (BB * KP1)          // 524416 score elements per memory
#define INV_T (1.0f / 0.07f)
#define XBLK  9                   // ceil(KP1/512)
#define NPART (BB * XBLK)         // score blocks (each handles BOTH memories)
#define MEMN  ((size_t)OUTSZ * DD)

#define SCORE_BLOCKS NPART                 // 1152
#define COPY_BLOCKS  2048
#define TOTAL_BLOCKS (SCORE_BLOCKS + COPY_BLOCKS)  // 3200

// Output layout (float32):
#define OFF_I2   ((size_t)0)
#define OFF_I3   ((size_t)NP)
#define OFF_M2   ((size_t)2 * NP)
#define OFF_M3   ((size_t)2 * NP + MEMN)

// Z-reduction scratch; every slot fully rewritten every launch.
__device__ float g_part[2 * NPART];

// ---------------------------------------------------------------------------
// Fused main kernel (Round-12 proven: 69.8us, ~94% of practical L2 cap).
// Score blocks handle BOTH banks per (b, k-chunk): one idx load feeds 8
// gather loads/thread. Streaming stores for all outputs.
// ---------------------------------------------------------------------------
template <bool VEC>
__global__ void __launch_bounds__(256, 4) fused_kernel(
    const float* __restrict__ z1,
    const float* __restrict__ mem2,
    const float* __restrict__ mem3,
    const int*   __restrict__ y,
    const int*   __restrict__ idx,
    float*       __restrict__ out)
{
    const int bid = blockIdx.x;
    const int tid = threadIdx.x;

    // ---------------- copy role ----------------
    const bool is_copy = (bid < 2 * SCORE_BLOCKS) ? (bid & 1) : true;
    if (is_copy) {
        const int cid = (bid < 2 * SCORE_BLOCKS)
                      ? (bid >> 1)
                      : (SCORE_BLOCKS + (bid - 2 * SCORE_BLOCKS));
        const size_t stride = (size_t)COPY_BLOCKS * 256;
        if (VEC) {
            const float4* __restrict__ s2 = (const float4*)mem2;
            const float4* __restrict__ s3 = (const float4*)mem3;
            float4* __restrict__ o2 = (float4*)(out + OFF_M2);
            float4* __restrict__ o3 = (float4*)(out + OFF_M3);
            const size_t n4 = MEMN / 4;
            for (size_t i = (size_t)cid * 256 + tid; i < n4; i += stride) {
                __stcs(&o2[i], s2[i]);
                __stcs(&o3[i], s3[i]);
            }
        } else {
            float* __restrict__ o2 = out + OFF_M2;
            float* __restrict__ o3 = out + OFF_M3;
            for (size_t i = (size_t)cid * 256 + tid; i < MEMN; i += stride) {
                __stcs(&o2[i], mem2[i]);
                __stcs(&o3[i], mem3[i]);
            }
        }
        return;
    }

    // ---------------- score role (both memories) ----------------
    const int sid = bid >> 1;            // 0..1151
    const int xb = sid % XBLK;
    const int b  = sid / XBLK;

    float* __restrict__ o2 = out + OFF_I2 + (size_t)b * KP1;
    float* __restrict__ o3 = out + OFF_I3 + (size_t)b * KP1;

    const int warp = tid >> 5;
    const int lane = tid & 31;
    const int g    = lane >> 3;   // group 0..3 within warp
    const int gl   = lane & 7;    // lane within group

    float4 zr[4];
    {
        const float* __restrict__ zb = z1 + b * DD;
        if (VEC) {
            const float4* __restrict__ z4 = (const float4*)zb;
            #pragma unroll
            for (int j = 0; j < 4; ++j) zr[j] = z4[j * 8 + gl];
        } else {
            #pragma unroll
            for (int j = 0; j < 4; ++j) {
                const int e = (j * 8 + gl) * 4;
                zr[j].x = zb[e + 0]; zr[j].y = zb[e + 1];
                zr[j].z = zb[e + 2]; zr[j].w = zb[e + 3];
            }
        }
    }

    const int yb = y[b];
    const int kbase = xb * 512;
    const int* __restrict__ idxb = idx + b * KP1;
    float local2 = 0.0f, local3 = 0.0f;

    int row_next;
    {
        const int k0 = kbase + warp * 4 + g;
        int r;
        if (k0 >= KP1)     r = 0;
        else if (k0 == 0)  r = yb;
        else               r = idxb[k0];
        row_next = r < 0 ? 0 : (r >= OUTSZ ? OUTSZ - 1 : r);
    }

    #pragma unroll 4
    for (int it = 0; it < 16; ++it) {
        const int k = kbase + it * 32 + warp * 4 + g;
        const bool valid = (k < KP1);
        const int row = row_next;

        const float* __restrict__ rf2 = mem2 + (size_t)row * DD;
        const float* __restrict__ rf3 = mem3 + (size_t)row * DD;

        float acc2, acc3;
        if (VEC) {
            const float4* __restrict__ r2 = (const float4*)rf2;
            const float4* __restrict__ r3 = (const float4*)rf3;
            float4 a0 = r2[0 * 8 + gl];
            float4 a1 = r2[1 * 8 + gl];
            float4 a2 = r2[2 * 8 + gl];
            float4 a3 = r2[3 * 8 + gl];
            float4 c0 = r3[0 * 8 + gl];
            float4 c1 = r3[1 * 8 + gl];
            float4 c2 = r3[2 * 8 + gl];
            float4 c3 = r3[3 * 8 + gl];

            {
                const int kn = k + 32;
                int r;
                if (it == 15 || kn >= KP1) r = 0;
                else                       r = idxb[kn];
                row_next = r < 0 ? 0 : (r >= OUTSZ ? OUTSZ - 1 : r);
            }

            acc2  = a0.x * zr[0].x; acc2 = fmaf(a0.y, zr[0].y, acc2);
            acc2 = fmaf(a0.z, zr[0].z, acc2); acc2 = fmaf(a0.w, zr[0].w, acc2);
            acc2 = fmaf(a1.x, zr[1].x, acc2); acc2 = fmaf(a1.y, zr[1].y, acc2);
            acc2 = fmaf(a1.z, zr[1].z, acc2); acc2 = fmaf(a1.w, zr[1].w, acc2);
            acc2 = fmaf(a2.x, zr[2].x, acc2); acc2 = fmaf(a2.y, zr[2].y, acc2);
            acc2 = fmaf(a2.z, zr[2].z, acc2); acc2 = fmaf(a2.w, zr[2].w, acc2);
            acc2 = fmaf(a3.x, zr[3].x, acc2); acc2 = fmaf(a3.y, zr[3].y, acc2);
            acc2 = fmaf(a3.z, zr[3].z, acc2); acc2 = fmaf(a3.w, zr[3].w, acc2);

            acc3  = c0.x * zr[0].x; acc3 = fmaf(c0.y, zr[0].y, acc3);
            acc3 = fmaf(c0.z, zr[0].z, acc3); acc3 = fmaf(c0.w, zr[0].w, acc3);
            acc3 = fmaf(c1.x, zr[1].x, acc3); acc3 = fmaf(c1.y, zr[1].y, acc3);
            acc3 = fmaf(c1.z, zr[1].z, acc3); acc3 = fmaf(c1.w, zr[1].w, acc3);
            acc3 = fmaf(c2.x, zr[2].x, acc3); acc3 = fmaf(c2.y, zr[2].y, acc3);
            acc3 = fmaf(c2.z, zr[2].z, acc3); acc3 = fmaf(c2.w, zr[2].w, acc3);
            acc3 = fmaf(c3.x, zr[3].x, acc3); acc3 = fmaf(c3.y, zr[3].y, acc3);
            acc3 = fmaf(c3.z, zr[3].z, acc3); acc3 = fmaf(c3.w, zr[3].w, acc3);
        } else {
            acc2 = 0.0f; acc3 = 0.0f;
            {
                const int kn = k + 32;
                int r;
                if (it == 15 || kn >= KP1) r = 0;
                else                       r = idxb[kn];
                row_next = r < 0 ? 0 : (r >= OUTSZ ? OUTSZ - 1 : r);
            }
            #pragma unroll
            for (int j = 0; j < 4; ++j) {
                const int e = (j * 8 + gl) * 4;
                acc2 = fmaf(rf2[e + 0], zr[j].x, acc2);
                acc2 = fmaf(rf2[e + 1], zr[j].y, acc2);
                acc2 = fmaf(rf2[e + 2], zr[j].z, acc2);
                acc2 = fmaf(rf2[e + 3], zr[j].w, acc2);
                acc3 = fmaf(rf3[e + 0], zr[j].x, acc3);
                acc3 = fmaf(rf3[e + 1], zr[j].y, acc3);
                acc3 = fmaf(rf3[e + 2], zr[j].z, acc3);
                acc3 = fmaf(rf3[e + 3], zr[j].w, acc3);
            }
        }

        acc2 += __shfl_xor_sync(0xffffffffu, acc2, 1);
        acc3 += __shfl_xor_sync(0xffffffffu, acc3, 1);
        acc2 += __shfl_xor_sync(0xffffffffu, acc2, 2);
        acc3 += __shfl_xor_sync(0xffffffffu, acc3, 2);
        acc2 += __shfl_xor_sync(0xffffffffu, acc2, 4);
        acc3 += __shfl_xor_sync(0xffffffffu, acc3, 4);

        if (valid && gl == 0) {
            const float s2 = __expf(acc2 * INV_T);
            const float s3 = __expf(acc3 * INV_T);
            __stcs(&o2[k], s2);
            __stcs(&o3[k], s3);
            local2 += s2;
            local3 += s3;
        }
    }

    __shared__ float red2[256], red3[256];
    red2[tid] = local2;
    red3[tid] = local3;
    __syncthreads();
    for (int off = 128; off > 0; off >>= 1) {
        if (tid < off) {
            red2[tid] += red2[tid + off];
            red3[tid] += red3[tid + off];
        }
        __syncthreads();
    }
    if (tid == 0) {
        g_part[sid]         = red2[0];
        g_part[NPART + sid] = red3[0];
    }
}

// ---------------------------------------------------------------------------
// Fused tail kernel: ONE launch replaces norm + update + fork/join.
//   blocks [0, NORM_BLOCKS)           : Z reduce (redundant per block) + scale
//   blocks [NORM_BLOCKS, +UPD_BLOCKS) : row updates, one WARP per (i,m) pair
// Both roles depend only on fused_kernel; no intra-kernel ordering needed
// (they touch disjoint output regions; update overwrites copied rows, and
// runs strictly after fused_kernel by launch order).
// ---------------------------------------------------------------------------
#define NORM_BLOCKS 512
#define UPD_BLOCKS  32     // 32 blocks * 8 warps = 256 warps = 256 (i,m) pairs
template <bool VEC>
__global__ void __launch_bounds__(256) tail_kernel(
    const float* __restrict__ z2,
    const float* __restrict__ z3,
    const float* __restrict__ mem2,
    const float* __restrict__ mem3,
    const int*   __restrict__ y,
    float*       __restrict__ out)
{
    const int tid = threadIdx.x;

    if (blockIdx.x < NORM_BLOCKS) {
        // ---------------- norm role ----------------
        float s0 = 0.0f, s1 = 0.0f;
        for (int i = tid; i < NPART; i += 256) {
            s0 += g_part[i];
            s1 += g_part[NPART + i];
        }
        __shared__ float r0[256], r1[256];
        r0[tid] = s0; r1[tid] = s1;
        __syncthreads();
        for (int off = 128; off > 0; off >>= 1) {
            if (tid < off) { r0[tid] += r0[tid + off]; r1[tid] += r1[tid + off]; }
            __syncthreads();
        }
        const float inv0 = 1.0f / (r0[0] / (float)NP * (float)OUTSZ);
        const float inv1 = 1.0f / (r1[0] / (float)NP * (float)OUTSZ);

        const int stride = NORM_BLOCKS * 256;
        for (int i = blockIdx.x * 256 + tid; i < 2 * NP; i += stride)
            __stcs(&out[i], out[i] * ((i < NP) ? inv0 : inv1));
        return;
    }

    // ---------------- update role: one warp per (i,m) ----------------
    const int warp = tid >> 5;
    const int l    = tid & 31;
    const int pair = (blockIdx.x - NORM_BLOCKS) * 8 + warp;  // 0..255
    const int i = pair >> 1;     // batch row
    const int m = pair & 1;      // memory select

    int yi = y[i];
    yi = yi < 0 ? 0 : (yi >= OUTSZ ? OUTSZ - 1 : yi);
    // last-duplicate-wins: this warp's write is dead if a later row hits yi
    bool dead = false;
    for (int j = i + 1; j < BB; ++j)
        dead = dead || (y[j] == yi);

    const float* __restrict__ mem = m ? mem3 : mem2;
    const float* __restrict__ z   = m ? z3   : z2;

    // each lane owns 4 contiguous elements (float4 if aligned)
    float4 zv, mv;
    if (VEC) {
        zv = ((const float4*)(z   + (size_t)i  * DD))[l];
        mv = ((const float4*)(mem + (size_t)yi * DD))[l];
    } else {
        const float* zp = z + (size_t)i * DD + l * 4;
        zv.x = zp[0]; zv.y = zp[1]; zv.z = zp[2]; zv.w = zp[3];
        const float* mp = mem + (size_t)yi * DD + l * 4;
        mv.x = mp[0]; mv.y = mp[1]; mv.z = mp[2]; mv.w = mp[3];
    }

    float4 v;
    v.x = 2.0f * zv.x - mv.x;
    v.y = 2.0f * zv.y - mv.y;
    v.z = 2.0f * zv.z - mv.z;
    v.w = 2.0f * zv.w - mv.w;

    float sq = v.x * v.x;
    sq = fmaf(v.y, v.y, sq);
    sq = fmaf(v.z, v.z, sq);
    sq = fmaf(v.w, v.w, sq);
    #pragma unroll
    for (int off = 16; off > 0; off >>= 1)
        sq += __shfl_xor_sync(0xffffffffu, sq, off);

    const float inv = 1.0f / sqrtf(sq);

    if (!dead) {
        float* __restrict__ om = out + (m ? OFF_M3 : OFF_M2);
        if (VEC) {
            float4 r;
            r.x = v.x * inv; r.y = v.y * inv; r.z = v.z * inv; r.w = v.w * inv;
            ((float4*)(om + (size_t)yi * DD))[l] = r;
        } else {
            float* q = om + (size_t)yi * DD + l * 4;
            q[0] = v.x * inv; q[1] = v.y * inv;
            q[2] = v.z * inv; q[3] = v.w * inv;
        }
    }
}

extern "C" void kernel_launch(void* const* d_in, const int* in_sizes, int n_in,
                              void* d_out, int out_size)
{
    // Identify inputs BY ELEMENT COUNT (order-robust):
    //   16384    -> z1, z2, z3           (relative order preserved)
    //   12800000 -> memory_z2, memory_z3 (relative order preserved)
    //   128      -> y
    //   524416   -> idx
    const float* zv[3]   = {0, 0, 0};
    const float* memv[2] = {0, 0};
    const int*   y   = 0;
    const int*   idx = 0;
    int nz = 0, nm = 0;
    for (int i = 0; i < n_in; ++i) {
        const int sz = in_sizes[i];
        if (sz == BB * DD) {
            if (nz < 3) zv[nz++] = (const float*)d_in[i];
        } else if (sz == (int)MEMN) {
            if (nm < 2) memv[nm++] = (const float*)d_in[i];
        } else if (sz == BB) {
            y = (const int*)d_in[i];
        } else if (sz == BB * KP1) {
            idx = (const int*)d_in[i];
        }
    }
    const float* z1   = zv[0];
    const float* z2   = zv[1];
    const float* z3   = zv[2];
    const float* mem2 = memv[0];
    const float* mem3 = memv[1];
    float* out = (float*)d_out;

    const bool vec = ((((uintptr_t)mem2) | ((uintptr_t)mem3)
                     | ((uintptr_t)z1) | ((uintptr_t)z2) | ((uintptr_t)z3)
                     | ((uintptr_t)out)) & 0xF) == 0;

    // 1) fused score(both banks) + bank-copy kernel
    if (vec)
        fused_kernel<true ><<<TOTAL_BLOCKS, 256>>>(z1, mem2, mem3, y, idx, out);
    else
        fused_kernel<false><<<TOTAL_BLOCKS, 256>>>(z1, mem2, mem3, y, idx, out);

    // 2) single tail kernel: norm + update in one launch
    if (vec)
        tail_kernel<true ><<<NORM_BLOCKS + UPD_BLOCKS, 256>>>(
            z2, z3, mem2, mem3, y, out);
    else
        tail_kernel<false><<<NORM_BLOCKS + UPD_BLOCKS, 256>>>(
            z2, z3, mem2, mem3, y, out);
}